// round 16
// baseline (speedup 1.0000x reference)
#include <cuda_runtime.h>
#include <cuda_fp16.h>
#include <cstdint>

#define D_DIM 1024
#define H_DIM 2048
#define E_NUM 8
#define T_MAX 4096
#define BM 128
#define MAX_TILES 72
#define MAX_ROWS  (MAX_TILES * BM)

#define BKW 64
#define UP_NK 16
#define DN_NK 32
#define STAGE_BYTES 49152
#define NSTAGE 4
#define GEMM_SMEM (NSTAGE * STAGE_BYTES + 1024)

// ---------------- device-global scratch ------------------------------------
__device__ int   g_counts[E_NUM];
__device__ int   g_tile_expert[MAX_TILES];
__device__ int   g_list[E_NUM * T_MAX];
__device__ float g_probs[2 * T_MAX];
__device__ int   g_gather[MAX_ROWS];
__device__ float g_rowprob[MAX_ROWS];
__device__ __half g_xH [(size_t)T_MAX * D_DIM];
__device__ __half g_w1H[(size_t)E_NUM * H_DIM * D_DIM];
__device__ __half g_w2H[(size_t)E_NUM * H_DIM * D_DIM];
__device__ __half g_w3H[(size_t)E_NUM * D_DIM * H_DIM];
__device__ __half g_hH [(size_t)MAX_ROWS * H_DIM];

// ---------------- side stream (load-time init) -------------------------------
static cudaStream_t g_s1 = 0;
static cudaEvent_t  g_ef = 0, g_e12 = 0, g_e3 = 0;
namespace {
struct SideInit {
    SideInit() {
        if (cudaStreamCreateWithFlags(&g_s1, cudaStreamNonBlocking) != cudaSuccess) g_s1 = 0;
        if (cudaEventCreateWithFlags(&g_ef,  cudaEventDisableTiming) != cudaSuccess) g_ef = 0;
        if (cudaEventCreateWithFlags(&g_e12, cudaEventDisableTiming) != cudaSuccess) g_e12 = 0;
        if (cudaEventCreateWithFlags(&g_e3,  cudaEventDisableTiming) != cudaSuccess) g_e3 = 0;
    }
};
SideInit s_side_init;
}

// ---------------- helpers ----------------------------------------------------
__device__ __forceinline__ uint32_t smem_u32(const void* p) {
    uint32_t a;
    asm("{ .reg .u64 t; cvta.to.shared.u64 t, %1; cvt.u32.u64 %0, t; }"
        : "=r"(a) : "l"(p));
    return a;
}
__device__ __forceinline__ void ldsm4(uint32_t& r0, uint32_t& r1, uint32_t& r2,
                                      uint32_t& r3, uint32_t addr) {
    asm volatile("ldmatrix.sync.aligned.m8n8.x4.shared.b16 {%0,%1,%2,%3}, [%4];"
                 : "=r"(r0), "=r"(r1), "=r"(r2), "=r"(r3) : "r"(addr));
}
__device__ __forceinline__ void mma16816(float* c, const uint32_t* a,
                                         const uint32_t* b) {
    asm volatile(
        "mma.sync.aligned.m16n8k16.row.col.f32.f16.f16.f32 "
        "{%0,%1,%2,%3},{%4,%5,%6,%7},{%8,%9},{%0,%1,%2,%3};"
        : "+f"(c[0]), "+f"(c[1]), "+f"(c[2]), "+f"(c[3])
        : "r"(a[0]), "r"(a[1]), "r"(a[2]), "r"(a[3]), "r"(b[0]), "r"(b[1]));
}
__device__ __forceinline__ void cp16(uint32_t dst, const void* src, int srcsize) {
    asm volatile("cp.async.cg.shared.global [%0], [%1], 16, %2;"
                 :: "r"(dst), "l"(src), "r"(srcsize) : "memory");
}
#define CP_COMMIT asm volatile("cp.async.commit_group;" ::: "memory")
template <int N>
__device__ __forceinline__ void cp_wait() {
    asm volatile("cp.async.wait_group %0;" :: "n"(N) : "memory");
}
__device__ __forceinline__ void red2(float* addr, float a, float b) {
    asm volatile("red.global.add.v2.f32 [%0], {%1, %2};"
                 :: "l"(addr), "f"(a), "f"(b) : "memory");
}
__device__ __forceinline__ float silu_f(float v) { return v / (1.0f + __expf(-v)); }
__device__ __forceinline__ int sw_off(int r, int c) {
    return r * 128 + ((c ^ (r & 7)) << 4);
}

// ---------------- K0: zero out + expert counters --------------------------------
__global__ void zero_out_kernel(float* __restrict__ out, int total4) {
    int i = blockIdx.x * blockDim.x + threadIdx.x;
    if (i < total4) *(float4*)(out + i * 4) = make_float4(0, 0, 0, 0);
    if (blockIdx.x == 0 && threadIdx.x < E_NUM) g_counts[threadIdx.x] = 0;
}

// ---------------- K1: router (fused x->fp16) -----------------------------------
__global__ void router_kernel(const float* __restrict__ x,
                              const float* __restrict__ gw, int T) {
    int warp = blockIdx.x * (blockDim.x >> 5) + (threadIdx.x >> 5);
    int lane = threadIdx.x & 31;
    if (warp >= T) return;
    const float* xr = x + (size_t)warp * D_DIM;
    __half* xh = g_xH + (size_t)warp * D_DIM;

    float acc[E_NUM];
#pragma unroll
    for (int e = 0; e < E_NUM; e++) acc[e] = 0.0f;
#pragma unroll
    for (int i = 0; i < D_DIM / 128; i++) {
        int d = i * 128 + lane * 4;
        float4 xv = *(const float4*)(xr + d);
        __half2 h0 = __floats2half2_rn(xv.x, xv.y);
        __half2 h1 = __floats2half2_rn(xv.z, xv.w);
        *(uint2*)(xh + d) = make_uint2(*(uint32_t*)&h0, *(uint32_t*)&h1);
#pragma unroll
        for (int e = 0; e < E_NUM; e++) {
            float4 gv = *(const float4*)(gw + e * D_DIM + d);
            acc[e] += xv.x * gv.x + xv.y * gv.y + xv.z * gv.z + xv.w * gv.w;
        }
    }
#pragma unroll
    for (int e = 0; e < E_NUM; e++) {
#pragma unroll
        for (int off = 16; off > 0; off >>= 1)
            acc[e] += __shfl_xor_sync(0xFFFFFFFFu, acc[e], off);
    }
    if (lane == 0) {
        int e0 = 0; float s0 = acc[0];
#pragma unroll
        for (int e = 1; e < E_NUM; e++) if (acc[e] > s0) { s0 = acc[e]; e0 = e; }
        int e1 = -1; float s1 = -3.4e38f;
#pragma unroll
        for (int e = 0; e < E_NUM; e++)
            if (e != e0 && acc[e] > s1) { s1 = acc[e]; e1 = e; }
        float x1 = __expf(s1 - s0);
        float inv = 1.0f / (1.0f + x1);
        int t = warp;
        g_probs[2 * t] = inv;
        g_probs[2 * t + 1] = x1 * inv;
        int j0 = atomicAdd(&g_counts[e0], 1);
        g_list[e0 * T_MAX + j0] = (t << 1);
        int j1 = atomicAdd(&g_counts[e1], 1);
        g_list[e1 * T_MAX + j1] = (t << 1) | 1;
    }
}

// ---------------- K2: build (inline scan, + per-row prob) ----------------------
__global__ void build_kernel() {
    __shared__ int s_exp, s_off, s_cnt;
    if (threadIdx.x == 0) {
        int off = 0, nt = 0, my_e = -1, my_off = 0, my_cnt = 0;
#pragma unroll
        for (int e = 0; e < E_NUM; e++) {
            int c = g_counts[e];
            int te = (c + BM - 1) / BM;
            if ((int)blockIdx.x >= nt && (int)blockIdx.x < nt + te) {
                my_e = e; my_off = off; my_cnt = c;
            }
            nt += te;
            off += te * BM;
        }
        g_tile_expert[blockIdx.x] = my_e;
        s_exp = my_e; s_off = my_off; s_cnt = my_cnt;
    }
    __syncthreads();
    int e = s_exp;
    int r = blockIdx.x * BM + threadIdx.x;
    if (e < 0) { g_gather[r] = -1; g_rowprob[r] = 0.0f; return; }
    int j = r - s_off;
    if (j < s_cnt) {
        int entry = g_list[e * T_MAX + j];
        g_gather[r] = entry >> 1;
        g_rowprob[r] = g_probs[entry];
    } else {
        g_gather[r] = -1;
        g_rowprob[r] = 0.0f;
    }
}

// ---------------- weight conversions (split by dependency) ---------------------
__global__ void conv_w12_kernel(const float* __restrict__ w1,
                                const float* __restrict__ w2, long n4) {
    long i = blockIdx.x * (long)blockDim.x + threadIdx.x;
    if (i >= 2 * n4) return;
    const float* src;
    __half* dst;
    long j;
    if (i < n4) { src = w1; dst = g_w1H; j = i; }
    else        { src = w2; dst = g_w2H; j = i - n4; }
    long eb = j * 4;
    float4 v = *(const float4*)(src + eb);
    __half2 h0 = __floats2half2_rn(v.x, v.y);
    __half2 h1 = __floats2half2_rn(v.z, v.w);
    *(uint2*)(dst + eb) = make_uint2(*(uint32_t*)&h0, *(uint32_t*)&h1);
}

__global__ void conv_w3_kernel(const float* __restrict__ w3, long n4) {
    long i = blockIdx.x * (long)blockDim.x + threadIdx.x;
    if (i >= n4) return;
    long eb = i * 4;
    float4 v = *(const float4*)(w3 + eb);
    __half2 h0 = __floats2half2_rn(v.x, v.y);
    __half2 h1 = __floats2half2_rn(v.z, v.w);
    *(uint2*)(g_w3H + eb) = make_uint2(*(uint32_t*)&h0, *(uint32_t*)&h1);
}

// ---------------- K4: up GEMM — R15 core (paired B-ldsm) -----------------------
__global__ void __launch_bounds__(512, 1) gemm_up_mma() {
    const int e = g_tile_expert[blockIdx.y];
    if (e < 0) return;
    extern __shared__ char raw[];
    char* dsm = (char*)(((uintptr_t)raw + 1023) & ~(uintptr_t)1023);
    __shared__ int sg[BM];
    const int tid = threadIdx.x;
    const int m0 = blockIdx.y * BM;
    const int bn0 = blockIdx.x * 128;
    if (tid < BM) sg[tid] = g_gather[m0 + tid];
    __syncthreads();
    const uint32_t sb = smem_u32(dsm);
    const int lane = tid & 31, wid = tid >> 5;
    const int wm = wid & 3, wn = wid >> 2;

    const char* asrc[2]; int asz[2]; int dA[2];
    const char* b1s[2];
    const size_t w2delta = (const char*)g_w2H - (const char*)g_w1H;
#pragma unroll
    for (int i = 0; i < 2; i++) {
        int idx = tid + i * 512;
        int r = idx >> 3, c = idx & 7;
        dA[i] = sw_off(r, c);
        int tok = sg[r];
        asrc[i] = (tok >= 0) ? (const char*)(g_xH + (size_t)tok * D_DIM + c * 8)
                             : (const char*)g_xH;
        asz[i] = (tok >= 0) ? 16 : 0;
        b1s[i] = (const char*)(g_w1H + ((size_t)e * H_DIM + bn0 + r) * D_DIM + c * 8);
    }

#define U_LOAD(KT) do {                                                         \
    const int _s = (KT) % NSTAGE;                                               \
    const uint32_t _b = sb + _s * STAGE_BYTES;                                  \
    const int _k = (KT) * (BKW * 2);                                            \
    _Pragma("unroll") for (int i = 0; i < 2; i++) {                             \
        cp16(_b + dA[i], asrc[i] + _k, asz[i]);                                 \
        cp16(_b + 16384 + dA[i], b1s[i] + _k, 16);                              \
        cp16(_b + 32768 + dA[i], b1s[i] + w2delta + _k, 16);                    \
    } } while (0)

    U_LOAD(0); CP_COMMIT;
    U_LOAD(1); CP_COMMIT;
    U_LOAD(2); CP_COMMIT;

    float cu[2][4][4], cv[2][4][4];
#pragma unroll
    for (int a = 0; a < 2; a++)
#pragma unroll
        for (int b = 0; b < 4; b++)
#pragma unroll
            for (int c = 0; c < 4; c++) { cu[a][b][c] = 0.0f; cv[a][b][c] = 0.0f; }

    const int ar0 = wm * 32 + (lane & 15);
    const int acs = (lane >> 4);

    for (int kt = 0; kt < UP_NK; kt++) {
        cp_wait<2>(); __syncthreads();
        if (kt + 3 < UP_NK) U_LOAD(kt + 3);
        CP_COMMIT;
        const uint32_t At  = sb + (kt % NSTAGE) * STAGE_BYTES;
        const uint32_t B1t = At + 16384;
        const uint32_t B2t = At + 32768;

        uint32_t afr[2][2][4];
#pragma unroll
        for (int mi = 0; mi < 2; mi++)
            ldsm4(afr[0][mi][0], afr[0][mi][1], afr[0][mi][2], afr[0][mi][3],
                  At + sw_off(ar0 + mi * 16, acs));
#pragma unroll
        for (int ks = 0; ks < 4; ks++) {
            const int cb = ks & 1, nb = cb ^ 1;
            if (ks < 3) {
#pragma unroll
                for (int mi = 0; mi < 2; mi++)
                    ldsm4(afr[nb][mi][0], afr[nb][mi][1], afr[nb][mi][2], afr[nb][mi][3],
                          At + sw_off(ar0 + mi * 16, (ks + 1) * 2 + acs));
            }
#pragma unroll
            for (int bj = 0; bj < 2; bj++) {
                int r = wn * 32 + bj * 16 + ((lane >> 4) << 3) + (lane & 7);
                int c = ks * 2 + ((lane >> 3) & 1);
                int off = sw_off(r, c);
                uint32_t q0, q1, q2, q3, p0, p1, p2, p3;
                ldsm4(q0, q1, q2, q3, B1t + off);
                ldsm4(p0, p1, p2, p3, B2t + off);
                { uint32_t b[2] = {q0, q1};
                  mma16816(cu[0][2 * bj], afr[cb][0], b);
                  mma16816(cu[1][2 * bj], afr[cb][1], b); }
                { uint32_t b[2] = {q2, q3};
                  mma16816(cu[0][2 * bj + 1], afr[cb][0], b);
                  mma16816(cu[1][2 * bj + 1], afr[cb][1], b); }
                { uint32_t b[2] = {p0, p1};
                  mma16816(cv[0][2 * bj], afr[cb][0], b);
                  mma16816(cv[1][2 * bj], afr[cb][1], b); }
                { uint32_t b[2] = {p2, p3};
                  mma16816(cv[0][2 * bj + 1], afr[cb][0], b);
                  mma16816(cv[1][2 * bj + 1], afr[cb][1], b); }
            }
        }
    }
#undef U_LOAD

#pragma unroll
    for (int mi = 0; mi < 2; mi++) {
#pragma unroll
        for (int nj = 0; nj < 4; nj++) {
            int r0 = m0 + wm * 32 + mi * 16 + (lane >> 2);
            int col = bn0 + wn * 32 + nj * 8 + (lane & 3) * 2;
#pragma unroll
            for (int h = 0; h < 2; h++) {
                int r = r0 + 8 * h;
                float f0 = silu_f(cu[mi][nj][2 * h])     * cv[mi][nj][2 * h];
                float f1 = silu_f(cu[mi][nj][2 * h + 1]) * cv[mi][nj][2 * h + 1];
                __half2 hh = __floats2half2_rn(f0, f1);
                *(__half2*)(g_hH + (size_t)r * H_DIM + col) = hh;
            }
        }
    }
}

// ---------------- K5: down GEMM — R15 core + fused combine ---------------------
__global__ void __launch_bounds__(512, 1) gemm_down_mma(float* __restrict__ out) {
    const int e = g_tile_expert[blockIdx.y];
    if (e < 0) return;
    extern __shared__ char raw[];
    char* dsm = (char*)(((uintptr_t)raw + 1023) & ~(uintptr_t)1023);
    const int tid = threadIdx.x;
    const int m0 = blockIdx.y * BM;
    const int bn0 = blockIdx.x * 256;
    const uint32_t sb = smem_u32(dsm);
    const int lane = tid & 31, wid = tid >> 5;
    const int wm = wid & 3, wn = wid >> 2;

    const char* asrc[2]; int dA[2];
    const char* bsrc[4]; int dB[4];
#pragma unroll
    for (int i = 0; i < 2; i++) {
        int idx = tid + i * 512;
        int r = idx >> 3, c = idx & 7;
        dA[i] = sw_off(r, c);
        asrc[i] = (const char*)(g_hH + (size_t)(m0 + r) * H_DIM + c * 8);
    }
#pragma unroll
    for (int i = 0; i < 4; i++) {
        int idx = tid + i * 512;
        int r = idx >> 3, c = idx & 7;
        dB[i] = sw_off(r, c);
        bsrc[i] = (const char*)(g_w3H + ((size_t)e * D_DIM + bn0 + r) * H_DIM + c * 8);
    }

#define D_LOAD(KT) do {                                                         \
    const int _s = (KT) % NSTAGE;                                               \
    const uint32_t _b = sb + _s * STAGE_BYTES;                                  \
    const long _k = (long)(KT) * (BKW * 2);                                     \
    _Pragma("unroll") for (int i = 0; i < 2; i++)                               \
        cp16(_b + dA[i], asrc[i] + _k, 16);                                     \
    _Pragma("unroll") for (int i = 0; i < 4; i++)                               \
        cp16(_b + 16384 + dB[i], bsrc[i] + _k, 16);                             \
    } while (0)

    D_LOAD(0); CP_COMMIT;
    D_LOAD(1); CP_COMMIT;
    D_LOAD(2); CP_COMMIT;

    float acc[2][8][4];
#pragma unroll
    for (int a = 0; a < 2; a++)
#pragma unroll
        for (int b = 0; b < 8; b++)
#pragma unroll
            for (int c = 0; c < 4; c++) acc[a][b][c] = 0.0f;

    const int ar0 = wm * 32 + (lane & 15);
    const int acs = (lane >> 4);

    for (int kt = 0; kt < DN_NK; kt++) {
        cp_wait<2>(); __syncthreads();
        if (kt + 3 < DN_NK) D_LOAD(kt + 3);
        CP_COMMIT;
        const uint32_t At = sb + (kt % NSTAGE) * STAGE_BYTES;
        const uint32_t Bt = At + 16384;

        uint32_t afr[2][2][4];
#pragma unroll
        for (int mi = 0; mi < 2; mi++)
            ldsm4(afr[0][mi][0], afr[0][mi][1], afr[0][mi][2], afr[0][mi][3],
                  At + sw_off(ar0 + mi * 16, acs));
#pragma unroll
        for (int ks = 0; ks < 4; ks++) {
            const int cb = ks & 1, nb = cb ^ 1;
            if (ks < 3) {
#pragma unroll
                for (int mi = 0; mi < 2; mi++)
                    ldsm4(afr[nb][mi][0], afr[nb][mi][1], afr[nb][mi][2], afr[nb][mi][3],
                          At + sw_off(ar0 + mi * 16, (ks + 1) * 2 + acs));
            }
#pragma unroll
            for (int bjp = 0; bjp < 2; bjp++) {
                const int bj0 = 2 * bjp, bj1 = bj0 + 1;
                int c = ks * 2 + ((lane >> 3) & 1);
                int rb = ((lane >> 4) << 3) + (lane & 7);
                uint32_t q0, q1, q2, q3, p0, p1, p2, p3;
                ldsm4(q0, q1, q2, q3, Bt + sw_off(wn * 64 + bj0 * 16 + rb, c));
                ldsm4(p0, p1, p2, p3, Bt + sw_off(wn * 64 + bj1 * 16 + rb, c));
                { uint32_t b[2] = {q0, q1};
                  mma16816(acc[0][2 * bj0], afr[cb][0], b);
                  mma16816(acc[1][2 * bj0], afr[cb][1], b); }
                { uint32_t b[2] = {q2, q3};
                  mma16816(acc[0][2 * bj0 + 1], afr[cb][0], b);
                  mma16816(acc[1][2 * bj0 + 1], afr[cb][1], b); }
                { uint32_t b[2] = {p0, p1};
                  mma16816(acc[0][2 * bj1], afr[cb][0], b);
                  mma16816(acc[1][2 * bj1], afr[cb][1], b); }
                { uint32_t b[2] = {p2, p3};
                  mma16816(acc[0][2 * bj1 + 1], afr[cb][0], b);
                  mma16816(acc[1][2 * bj1 + 1], afr[cb][1], b); }
            }
        }
    }
#undef D_LOAD

    int   tk[2][2];
    float pp[2][2];
#pragma unroll
    for (int mi = 0; mi < 2; mi++) {
        int r0 = m0 + wm * 32 + mi * 16 + (lane >> 2);
#pragma unroll
        for (int h = 0; h < 2; h++) {
            int r = r0 + 8 * h;
            tk[mi][h] = g_gather[r];
            pp[mi][h] = g_rowprob[r];
        }
    }
#pragma unroll
    for (int mi = 0; mi < 2; mi++) {
#pragma unroll
        for (int nj = 0; nj < 8; nj++) {
            int col = bn0 + wn * 64 + nj * 8 + (lane & 3) * 2;
            if (tk[mi][0] >= 0)
                red2(out + (size_t)tk[mi][0] * D_DIM + col,
                     pp[mi][0] * acc[mi][nj][0], pp[mi][0] * acc[mi][nj][1]);
            if (tk[mi][1] >= 0)
                red2(out + (size_t)tk[mi][1] * D_DIM + col,
                     pp[mi][1] * acc[mi][nj][2], pp[mi][1] * acc[mi][nj][3]);
        }
    }
}

// ---------------- launch ---------------------------------------------------------
extern "C" void kernel_launch(void* const* d_in, const int* in_sizes, int n_in,
                              void* d_out, int out_size) {
    const float* x  = (const float*)d_in[0];
    const float* gw = (const float*)d_in[1];
    const float* w1 = (const float*)d_in[2];
    const float* w2 = (const float*)d_in[3];
    const float* w3 = (const float*)d_in[4];
    float* out = (float*)d_out;

    int T = in_sizes[0] / D_DIM;
    if (T > T_MAX) T = T_MAX;
    int m_tiles = (2 * T) / BM + E_NUM;
    if (m_tiles > MAX_TILES) m_tiles = MAX_TILES;

    cudaFuncSetAttribute(gemm_up_mma,   cudaFuncAttributeMaxDynamicSharedMemorySize, GEMM_SMEM);
    cudaFuncSetAttribute(gemm_down_mma, cudaFuncAttributeMaxDynamicSharedMemorySize, GEMM_SMEM);

    long n4 = (long)E_NUM * H_DIM * D_DIM / 4;
    bool fork = (g_s1 != 0 && g_ef != 0 && g_e12 != 0 && g_e3 != 0);

    // side stream: conv(w1,w2) first (gates gemm_up), then conv(w3) (gates
    // gemm_down only — overlaps gemm_up's head).
    if (fork) {
        cudaEventRecord(g_ef, 0);
        cudaStreamWaitEvent(g_s1, g_ef, 0);
        conv_w12_kernel<<<(int)((2 * n4 + 255) / 256), 256, 0, g_s1>>>(w1, w2, n4);
        cudaEventRecord(g_e12, g_s1);
        conv_w3_kernel<<<(int)((n4 + 255) / 256), 256, 0, g_s1>>>(w3, n4);
        cudaEventRecord(g_e3, g_s1);
    }

    int out4 = T * (D_DIM / 4);
    zero_out_kernel<<<(out4 + 255) / 256, 256>>>(out, out4);
    router_kernel<<<(T + 7) / 8, 256>>>(x, gw, T);
    build_kernel<<<m_tiles, BM>>>();

    if (fork) {
        cudaStreamWaitEvent(0, g_e12, 0);
    } else {
        conv_w12_kernel<<<(int)((2 * n4 + 255) / 256), 256>>>(w1, w2, n4);
        conv_w3_kernel<<<(int)((n4 + 255) / 256), 256>>>(w3, n4);
    }

    gemm_up_mma<<<dim3(H_DIM / 128, m_tiles), 512, GEMM_SMEM>>>();

    if (fork) cudaStreamWaitEvent(0, g_e3, 0);
    gemm_down_mma<<<dim3(D_DIM / 256, m_tiles), 512, GEMM_SMEM>>>(out);
}

// round 17
// speedup vs baseline: 1.0281x; 1.0281x over previous
#include <cuda_runtime.h>
#include <cuda_fp16.h>
#include <cstdint>

#define D_DIM 1024
#define H_DIM 2048
#define E_NUM 8
#define T_MAX 4096
#define BM 128
#define MAX_TILES 72
#define MAX_ROWS  (MAX_TILES * BM)

#define BKW 64
#define UP_NK 16
#define DN_NK 32
#define STAGE_BYTES 49152
#define NSTAGE 4
#define GEMM_SMEM (NSTAGE * STAGE_BYTES + 1024)

// ---------------- device-global scratch ------------------------------------
__device__ int   g_counts[E_NUM];
__device__ int   g_tile_expert[MAX_TILES];
__device__ int   g_list[E_NUM * T_MAX];
__device__ float g_probs[2 * T_MAX];
__device__ int   g_gather[MAX_ROWS];
__device__ float g_rowprob[MAX_ROWS];
__device__ __half g_xH [(size_t)T_MAX * D_DIM];
__device__ __half g_w1H[(size_t)E_NUM * H_DIM * D_DIM];
__device__ __half g_w2H[(size_t)E_NUM * H_DIM * D_DIM];
__device__ __half g_w3H[(size_t)E_NUM * D_DIM * H_DIM];
__device__ __half g_hH [(size_t)MAX_ROWS * H_DIM];

// ---------------- side stream (load-time init) -------------------------------
static cudaStream_t g_s1 = 0;
static cudaEvent_t  g_ef = 0, g_ej = 0;
namespace {
struct SideInit {
    SideInit() {
        if (cudaStreamCreateWithFlags(&g_s1, cudaStreamNonBlocking) != cudaSuccess) g_s1 = 0;
        if (cudaEventCreateWithFlags(&g_ef, cudaEventDisableTiming) != cudaSuccess) g_ef = 0;
        if (cudaEventCreateWithFlags(&g_ej, cudaEventDisableTiming) != cudaSuccess) g_ej = 0;
    }
};
SideInit s_side_init;
}

// ---------------- helpers ----------------------------------------------------
__device__ __forceinline__ uint32_t smem_u32(const void* p) {
    uint32_t a;
    asm("{ .reg .u64 t; cvta.to.shared.u64 t, %1; cvt.u32.u64 %0, t; }"
        : "=r"(a) : "l"(p));
    return a;
}
__device__ __forceinline__ void ldsm4(uint32_t& r0, uint32_t& r1, uint32_t& r2,
                                      uint32_t& r3, uint32_t addr) {
    asm volatile("ldmatrix.sync.aligned.m8n8.x4.shared.b16 {%0,%1,%2,%3}, [%4];"
                 : "=r"(r0), "=r"(r1), "=r"(r2), "=r"(r3) : "r"(addr));
}
__device__ __forceinline__ void mma16816(float* c, const uint32_t* a,
                                         const uint32_t* b) {
    asm volatile(
        "mma.sync.aligned.m16n8k16.row.col.f32.f16.f16.f32 "
        "{%0,%1,%2,%3},{%4,%5,%6,%7},{%8,%9},{%0,%1,%2,%3};"
        : "+f"(c[0]), "+f"(c[1]), "+f"(c[2]), "+f"(c[3])
        : "r"(a[0]), "r"(a[1]), "r"(a[2]), "r"(a[3]), "r"(b[0]), "r"(b[1]));
}
__device__ __forceinline__ void cp16(uint32_t dst, const void* src, int srcsize) {
    asm volatile("cp.async.cg.shared.global [%0], [%1], 16, %2;"
                 :: "r"(dst), "l"(src), "r"(srcsize) : "memory");
}
#define CP_COMMIT asm volatile("cp.async.commit_group;" ::: "memory")
template <int N>
__device__ __forceinline__ void cp_wait() {
    asm volatile("cp.async.wait_group %0;" :: "n"(N) : "memory");
}
__device__ __forceinline__ void red2(float* addr, float a, float b) {
    asm volatile("red.global.add.v2.f32 [%0], {%1, %2};"
                 :: "l"(addr), "f"(a), "f"(b) : "memory");
}
__device__ __forceinline__ float silu_f(float v) { return v / (1.0f + __expf(-v)); }
__device__ __forceinline__ int sw_off(int r, int c) {
    return r * 128 + ((c ^ (r & 7)) << 4);
}

// ---------------- K0: zero out + expert counters --------------------------------
__global__ void zero_out_kernel(float* __restrict__ out, int total4) {
    int i = blockIdx.x * blockDim.x + threadIdx.x;
    if (i < total4) *(float4*)(out + i * 4) = make_float4(0, 0, 0, 0);
    if (blockIdx.x == 0 && threadIdx.x < E_NUM) g_counts[threadIdx.x] = 0;
}

// ---------------- K1: router (fused x->fp16) -----------------------------------
__global__ void router_kernel(const float* __restrict__ x,
                              const float* __restrict__ gw, int T) {
    int warp = blockIdx.x * (blockDim.x >> 5) + (threadIdx.x >> 5);
    int lane = threadIdx.x & 31;
    if (warp >= T) return;
    const float* xr = x + (size_t)warp * D_DIM;
    __half* xh = g_xH + (size_t)warp * D_DIM;

    float acc[E_NUM];
#pragma unroll
    for (int e = 0; e < E_NUM; e++) acc[e] = 0.0f;
#pragma unroll
    for (int i = 0; i < D_DIM / 128; i++) {
        int d = i * 128 + lane * 4;
        float4 xv = *(const float4*)(xr + d);
        __half2 h0 = __floats2half2_rn(xv.x, xv.y);
        __half2 h1 = __floats2half2_rn(xv.z, xv.w);
        *(uint2*)(xh + d) = make_uint2(*(uint32_t*)&h0, *(uint32_t*)&h1);
#pragma unroll
        for (int e = 0; e < E_NUM; e++) {
            float4 gv = *(const float4*)(gw + e * D_DIM + d);
            acc[e] += xv.x * gv.x + xv.y * gv.y + xv.z * gv.z + xv.w * gv.w;
        }
    }
#pragma unroll
    for (int e = 0; e < E_NUM; e++) {
#pragma unroll
        for (int off = 16; off > 0; off >>= 1)
            acc[e] += __shfl_xor_sync(0xFFFFFFFFu, acc[e], off);
    }
    if (lane == 0) {
        int e0 = 0; float s0 = acc[0];
#pragma unroll
        for (int e = 1; e < E_NUM; e++) if (acc[e] > s0) { s0 = acc[e]; e0 = e; }
        int e1 = -1; float s1 = -3.4e38f;
#pragma unroll
        for (int e = 0; e < E_NUM; e++)
            if (e != e0 && acc[e] > s1) { s1 = acc[e]; e1 = e; }
        float x1 = __expf(s1 - s0);
        float inv = 1.0f / (1.0f + x1);
        int t = warp;
        g_probs[2 * t] = inv;
        g_probs[2 * t + 1] = x1 * inv;
        int j0 = atomicAdd(&g_counts[e0], 1);
        g_list[e0 * T_MAX + j0] = (t << 1);
        int j1 = atomicAdd(&g_counts[e1], 1);
        g_list[e1 * T_MAX + j1] = (t << 1) | 1;
    }
}

// ---------------- K2: build (inline scan, + per-row prob) ----------------------
__global__ void build_kernel() {
    __shared__ int s_exp, s_off, s_cnt;
    if (threadIdx.x == 0) {
        int off = 0, nt = 0, my_e = -1, my_off = 0, my_cnt = 0;
#pragma unroll
        for (int e = 0; e < E_NUM; e++) {
            int c = g_counts[e];
            int te = (c + BM - 1) / BM;
            if ((int)blockIdx.x >= nt && (int)blockIdx.x < nt + te) {
                my_e = e; my_off = off; my_cnt = c;
            }
            nt += te;
            off += te * BM;
        }
        g_tile_expert[blockIdx.x] = my_e;
        s_exp = my_e; s_off = my_off; s_cnt = my_cnt;
    }
    __syncthreads();
    int e = s_exp;
    int r = blockIdx.x * BM + threadIdx.x;
    if (e < 0) { g_gather[r] = -1; g_rowprob[r] = 0.0f; return; }
    int j = r - s_off;
    if (j < s_cnt) {
        int entry = g_list[e * T_MAX + j];
        g_gather[r] = entry >> 1;
        g_rowprob[r] = g_probs[entry];
    } else {
        g_gather[r] = -1;
        g_rowprob[r] = 0.0f;
    }
}

// ---------------- weight conversion: 32B per thread ----------------------------
__global__ void conv_w_all_kernel(const float* __restrict__ w1,
                                  const float* __restrict__ w2,
                                  const float* __restrict__ w3, long n8) {
    long i = blockIdx.x * (long)blockDim.x + threadIdx.x;
    if (i >= 3 * n8) return;
    const float* src;
    __half* dst;
    long j;
    if (i < n8)           { src = w1; dst = g_w1H; j = i; }
    else if (i < 2 * n8)  { src = w2; dst = g_w2H; j = i - n8; }
    else                  { src = w3; dst = g_w3H; j = i - 2 * n8; }
    long eb = j * 8;
    float4 v0 = *(const float4*)(src + eb);
    float4 v1 = *(const float4*)(src + eb + 4);
    __half2 h0 = __floats2half2_rn(v0.x, v0.y);
    __half2 h1 = __floats2half2_rn(v0.z, v0.w);
    __half2 h2 = __floats2half2_rn(v1.x, v1.y);
    __half2 h3 = __floats2half2_rn(v1.z, v1.w);
    uint4 o = make_uint4(*(uint32_t*)&h0, *(uint32_t*)&h1,
                         *(uint32_t*)&h2, *(uint32_t*)&h3);
    *(uint4*)(dst + eb) = o;
}

// ---------------- K4: up GEMM — R15 core (paired B-ldsm) -----------------------
__global__ void __launch_bounds__(512, 1) gemm_up_mma() {
    const int e = g_tile_expert[blockIdx.y];
    if (e < 0) return;
    extern __shared__ char raw[];
    char* dsm = (char*)(((uintptr_t)raw + 1023) & ~(uintptr_t)1023);
    __shared__ int sg[BM];
    const int tid = threadIdx.x;
    const int m0 = blockIdx.y * BM;
    const int bn0 = blockIdx.x * 128;
    if (tid < BM) sg[tid] = g_gather[m0 + tid];
    __syncthreads();
    const uint32_t sb = smem_u32(dsm);
    const int lane = tid & 31, wid = tid >> 5;
    const int wm = wid & 3, wn = wid >> 2;

    const char* asrc[2]; int asz[2]; int dA[2];
    const char* b1s[2];
    const size_t w2delta = (const char*)g_w2H - (const char*)g_w1H;
#pragma unroll
    for (int i = 0; i < 2; i++) {
        int idx = tid + i * 512;
        int r = idx >> 3, c = idx & 7;
        dA[i] = sw_off(r, c);
        int tok = sg[r];
        asrc[i] = (tok >= 0) ? (const char*)(g_xH + (size_t)tok * D_DIM + c * 8)
                             : (const char*)g_xH;
        asz[i] = (tok >= 0) ? 16 : 0;
        b1s[i] = (const char*)(g_w1H + ((size_t)e * H_DIM + bn0 + r) * D_DIM + c * 8);
    }

#define U_LOAD(KT) do {                                                         \
    const int _s = (KT) % NSTAGE;                                               \
    const uint32_t _b = sb + _s * STAGE_BYTES;                                  \
    const int _k = (KT) * (BKW * 2);                                            \
    _Pragma("unroll") for (int i = 0; i < 2; i++) {                             \
        cp16(_b + dA[i], asrc[i] + _k, asz[i]);                                 \
        cp16(_b + 16384 + dA[i], b1s[i] + _k, 16);                              \
        cp16(_b + 32768 + dA[i], b1s[i] + w2delta + _k, 16);                    \
    } } while (0)

    U_LOAD(0); CP_COMMIT;
    U_LOAD(1); CP_COMMIT;
    U_LOAD(2); CP_COMMIT;

    float cu[2][4][4], cv[2][4][4];
#pragma unroll
    for (int a = 0; a < 2; a++)
#pragma unroll
        for (int b = 0; b < 4; b++)
#pragma unroll
            for (int c = 0; c < 4; c++) { cu[a][b][c] = 0.0f; cv[a][b][c] = 0.0f; }

    const int ar0 = wm * 32 + (lane & 15);
    const int acs = (lane >> 4);

    for (int kt = 0; kt < UP_NK; kt++) {
        cp_wait<2>(); __syncthreads();
        if (kt + 3 < UP_NK) U_LOAD(kt + 3);
        CP_COMMIT;
        const uint32_t At  = sb + (kt % NSTAGE) * STAGE_BYTES;
        const uint32_t B1t = At + 16384;
        const uint32_t B2t = At + 32768;

        uint32_t afr[2][2][4];
#pragma unroll
        for (int mi = 0; mi < 2; mi++)
            ldsm4(afr[0][mi][0], afr[0][mi][1], afr[0][mi][2], afr[0][mi][3],
                  At + sw_off(ar0 + mi * 16, acs));
#pragma unroll
        for (int ks = 0; ks < 4; ks++) {
            const int cb = ks & 1, nb = cb ^ 1;
            if (ks < 3) {
#pragma unroll
                for (int mi = 0; mi < 2; mi++)
                    ldsm4(afr[nb][mi][0], afr[nb][mi][1], afr[nb][mi][2], afr[nb][mi][3],
                          At + sw_off(ar0 + mi * 16, (ks + 1) * 2 + acs));
            }
#pragma unroll
            for (int bj = 0; bj < 2; bj++) {
                int r = wn * 32 + bj * 16 + ((lane >> 4) << 3) + (lane & 7);
                int c = ks * 2 + ((lane >> 3) & 1);
                int off = sw_off(r, c);
                uint32_t q0, q1, q2, q3, p0, p1, p2, p3;
                ldsm4(q0, q1, q2, q3, B1t + off);
                ldsm4(p0, p1, p2, p3, B2t + off);
                { uint32_t b[2] = {q0, q1};
                  mma16816(cu[0][2 * bj], afr[cb][0], b);
                  mma16816(cu[1][2 * bj], afr[cb][1], b); }
                { uint32_t b[2] = {q2, q3};
                  mma16816(cu[0][2 * bj + 1], afr[cb][0], b);
                  mma16816(cu[1][2 * bj + 1], afr[cb][1], b); }
                { uint32_t b[2] = {p0, p1};
                  mma16816(cv[0][2 * bj], afr[cb][0], b);
                  mma16816(cv[1][2 * bj], afr[cb][1], b); }
                { uint32_t b[2] = {p2, p3};
                  mma16816(cv[0][2 * bj + 1], afr[cb][0], b);
                  mma16816(cv[1][2 * bj + 1], afr[cb][1], b); }
            }
        }
    }
#undef U_LOAD

#pragma unroll
    for (int mi = 0; mi < 2; mi++) {
#pragma unroll
        for (int nj = 0; nj < 4; nj++) {
            int r0 = m0 + wm * 32 + mi * 16 + (lane >> 2);
            int col = bn0 + wn * 32 + nj * 8 + (lane & 3) * 2;
#pragma unroll
            for (int h = 0; h < 2; h++) {
                int r = r0 + 8 * h;
                float f0 = silu_f(cu[mi][nj][2 * h])     * cv[mi][nj][2 * h];
                float f1 = silu_f(cu[mi][nj][2 * h + 1]) * cv[mi][nj][2 * h + 1];
                __half2 hh = __floats2half2_rn(f0, f1);
                *(__half2*)(g_hH + (size_t)r * H_DIM + col) = hh;
            }
        }
    }
}

// ---------------- K5: down GEMM — R15 core + fused combine ---------------------
__global__ void __launch_bounds__(512, 1) gemm_down_mma(float* __restrict__ out) {
    const int e = g_tile_expert[blockIdx.y];
    if (e < 0) return;
    extern __shared__ char raw[];
    char* dsm = (char*)(((uintptr_t)raw + 1023) & ~(uintptr_t)1023);
    const int tid = threadIdx.x;
    const int m0 = blockIdx.y * BM;
    const int bn0 = blockIdx.x * 256;
    const uint32_t sb = smem_u32(dsm);
    const int lane = tid & 31, wid = tid >> 5;
    const int wm = wid & 3, wn = wid >> 2;

    const char* asrc[2]; int dA[2];
    const char* bsrc[4]; int dB[4];
#pragma unroll
    for (int i = 0; i < 2; i++) {
        int idx = tid + i * 512;
        int r = idx >> 3, c = idx & 7;
        dA[i] = sw_off(r, c);
        asrc[i] = (const char*)(g_hH + (size_t)(m0 + r) * H_DIM + c * 8);
    }
#pragma unroll
    for (int i = 0; i < 4; i++) {
        int idx = tid + i * 512;
        int r = idx >> 3, c = idx & 7;
        dB[i] = sw_off(r, c);
        bsrc[i] = (const char*)(g_w3H + ((size_t)e * D_DIM + bn0 + r) * H_DIM + c * 8);
    }

#define D_LOAD(KT) do {                                                         \
    const int _s = (KT) % NSTAGE;                                               \
    const uint32_t _b = sb + _s * STAGE_BYTES;                                  \
    const long _k = (long)(KT) * (BKW * 2);                                     \
    _Pragma("unroll") for (int i = 0; i < 2; i++)                               \
        cp16(_b + dA[i], asrc[i] + _k, 16);                                     \
    _Pragma("unroll") for (int i = 0; i < 4; i++)                               \
        cp16(_b + 16384 + dB[i], bsrc[i] + _k, 16);                             \
    } while (0)

    D_LOAD(0); CP_COMMIT;
    D_LOAD(1); CP_COMMIT;
    D_LOAD(2); CP_COMMIT;

    float acc[2][8][4];
#pragma unroll
    for (int a = 0; a < 2; a++)
#pragma unroll
        for (int b = 0; b < 8; b++)
#pragma unroll
            for (int c = 0; c < 4; c++) acc[a][b][c] = 0.0f;

    const int ar0 = wm * 32 + (lane & 15);
    const int acs = (lane >> 4);

    for (int kt = 0; kt < DN_NK; kt++) {
        cp_wait<2>(); __syncthreads();
        if (kt + 3 < DN_NK) D_LOAD(kt + 3);
        CP_COMMIT;
        const uint32_t At = sb + (kt % NSTAGE) * STAGE_BYTES;
        const uint32_t Bt = At + 16384;

        uint32_t afr[2][2][4];
#pragma unroll
        for (int mi = 0; mi < 2; mi++)
            ldsm4(afr[0][mi][0], afr[0][mi][1], afr[0][mi][2], afr[0][mi][3],
                  At + sw_off(ar0 + mi * 16, acs));
#pragma unroll
        for (int ks = 0; ks < 4; ks++) {
            const int cb = ks & 1, nb = cb ^ 1;
            if (ks < 3) {
#pragma unroll
                for (int mi = 0; mi < 2; mi++)
                    ldsm4(afr[nb][mi][0], afr[nb][mi][1], afr[nb][mi][2], afr[nb][mi][3],
                          At + sw_off(ar0 + mi * 16, (ks + 1) * 2 + acs));
            }
#pragma unroll
            for (int bjp = 0; bjp < 2; bjp++) {
                const int bj0 = 2 * bjp, bj1 = bj0 + 1;
                int c = ks * 2 + ((lane >> 3) & 1);
                int rb = ((lane >> 4) << 3) + (lane & 7);
                uint32_t q0, q1, q2, q3, p0, p1, p2, p3;
                ldsm4(q0, q1, q2, q3, Bt + sw_off(wn * 64 + bj0 * 16 + rb, c));
                ldsm4(p0, p1, p2, p3, Bt + sw_off(wn * 64 + bj1 * 16 + rb, c));
                { uint32_t b[2] = {q0, q1};
                  mma16816(acc[0][2 * bj0], afr[cb][0], b);
                  mma16816(acc[1][2 * bj0], afr[cb][1], b); }
                { uint32_t b[2] = {q2, q3};
                  mma16816(acc[0][2 * bj0 + 1], afr[cb][0], b);
                  mma16816(acc[1][2 * bj0 + 1], afr[cb][1], b); }
                { uint32_t b[2] = {p0, p1};
                  mma16816(acc[0][2 * bj1], afr[cb][0], b);
                  mma16816(acc[1][2 * bj1], afr[cb][1], b); }
                { uint32_t b[2] = {p2, p3};
                  mma16816(acc[0][2 * bj1 + 1], afr[cb][0], b);
                  mma16816(acc[1][2 * bj1 + 1], afr[cb][1], b); }
            }
        }
    }
#undef D_LOAD

    int   tk[2][2];
    float pp[2][2];
#pragma unroll
    for (int mi = 0; mi < 2; mi++) {
        int r0 = m0 + wm * 32 + mi * 16 + (lane >> 2);
#pragma unroll
        for (int h = 0; h < 2; h++) {
            int r = r0 + 8 * h;
            tk[mi][h] = g_gather[r];
            pp[mi][h] = g_rowprob[r];
        }
    }
#pragma unroll
    for (int mi = 0; mi < 2; mi++) {
#pragma unroll
        for (int nj = 0; nj < 8; nj++) {
            int col = bn0 + wn * 64 + nj * 8 + (lane & 3) * 2;
            if (tk[mi][0] >= 0)
                red2(out + (size_t)tk[mi][0] * D_DIM + col,
                     pp[mi][0] * acc[mi][nj][0], pp[mi][0] * acc[mi][nj][1]);
            if (tk[mi][1] >= 0)
                red2(out + (size_t)tk[mi][1] * D_DIM + col,
                     pp[mi][1] * acc[mi][nj][2], pp[mi][1] * acc[mi][nj][3]);
        }
    }
}

// ---------------- launch ---------------------------------------------------------
extern "C" void kernel_launch(void* const* d_in, const int* in_sizes, int n_in,
                              void* d_out, int out_size) {
    const float* x  = (const float*)d_in[0];
    const float* gw = (const float*)d_in[1];
    const float* w1 = (const float*)d_in[2];
    const float* w2 = (const float*)d_in[3];
    const float* w3 = (const float*)d_in[4];
    float* out = (float*)d_out;

    int T = in_sizes[0] / D_DIM;
    if (T > T_MAX) T = T_MAX;
    int m_tiles = (2 * T) / BM + E_NUM;
    if (m_tiles > MAX_TILES) m_tiles = MAX_TILES;

    cudaFuncSetAttribute(gemm_up_mma,   cudaFuncAttributeMaxDynamicSharedMemorySize, GEMM_SMEM);
    cudaFuncSetAttribute(gemm_down_mma, cudaFuncAttributeMaxDynamicSharedMemorySize, GEMM_SMEM);

    long n8 = (long)E_NUM * H_DIM * D_DIM / 8;
    bool fork = (g_s1 != 0 && g_ef != 0 && g_ej != 0);

    if (fork) {
        cudaEventRecord(g_ef, 0);
        cudaStreamWaitEvent(g_s1, g_ef, 0);
        conv_w_all_kernel<<<(int)((3 * n8 + 255) / 256), 256, 0, g_s1>>>(w1, w2, w3, n8);
        cudaEventRecord(g_ej, g_s1);
    }

    int out4 = T * (D_DIM / 4);
    zero_out_kernel<<<(out4 + 255) / 256, 256>>>(out, out4);
    router_kernel<<<(T + 7) / 8, 256>>>(x, gw, T);
    build_kernel<<<m_tiles, BM>>>();

    if (fork) cudaStreamWaitEvent(0, g_ej, 0);
    else conv_w_all_kernel<<<(int)((3 * n8 + 255) / 256), 256>>>(w1, w2, w3, n8);

    gemm_up_mma<<<dim3(H_DIM / 128, m_tiles), 512, GEMM_SMEM>>>();
    gemm_down_mma<<<dim3(D_DIM / 256, m_tiles), 512, GEMM_SMEM>>>(out);
}